// round 11
// baseline (speedup 1.0000x reference)
#include <cuda_runtime.h>
#include <math.h>
#include <float.h>

#define N_PTS 32768
#define C_IN 6
#define H_DIM 64
#define M_PTS 8192
#define KF 32
#define KN 16
#define KS 8
#define TILE 2048
#define CAP 64
#define QPB 64          // queries per block
#define HALF 1024       // candidates per sub per tile

// ---------------- scratch (no dynamic allocation allowed) ----------------
__device__ float  g_z1[N_PTS * H_DIM];
__device__ float  g_z2[N_PTS * H_DIM];
__device__ float  g_s[N_PTS];
__device__ float  g_bn[4 * H_DIM];
__device__ double g_acc[6];

__global__ void k_zero() {
    int t = threadIdx.x;
    if (t < 4 * H_DIM) g_bn[t] = 0.0f;
    if (t < 6) g_acc[t] = 0.0;
}

__device__ __forceinline__ float gelu_exact(float x) {
    return 0.5f * x * (1.0f + erff(x * 0.70710678118654752f));
}

// sorted top-32 insert (strict < => earlier-stream wins ties)
__device__ __forceinline__ void insert32(float (&dist)[KF], int (&idx)[KF],
                                         float cd, int ci) {
#pragma unroll
    for (int k = 0; k < KF; k++) {
        bool p = cd < dist[k];
        float nd = p ? cd : dist[k];
        float xd = p ? dist[k] : cd;
        int   ni = p ? ci : idx[k];
        int   xi = p ? idx[k] : ci;
        dist[k] = nd; cd = xd;
        idx[k]  = ni; ci = xi;
    }
}

// ---------------- MLP stage 1 ----------------
__global__ void k_mlp1(const float* __restrict__ feat,
                       const float* __restrict__ W1,
                       const float* __restrict__ b1) {
    __shared__ float sW[C_IN * H_DIM];
    __shared__ float sb[H_DIM];
    __shared__ float s_sum[H_DIM], s_sq[H_DIM];
    int t = threadIdx.x;
    for (int i = t; i < C_IN * H_DIM; i += blockDim.x) sW[i] = W1[i];
    if (t < H_DIM) { sb[t] = b1[t]; s_sum[t] = 0.0f; s_sq[t] = 0.0f; }
    __syncthreads();

    int row = blockIdx.x * blockDim.x + t;
    float f[C_IN];
#pragma unroll
    for (int c = 0; c < C_IN; c++) f[c] = feat[row * C_IN + c];

    int lane = t & 31;
#pragma unroll
    for (int h = 0; h < H_DIM; h++) {
        float a = sb[h];
#pragma unroll
        for (int c = 0; c < C_IN; c++) a = fmaf(f[c], sW[c * H_DIM + h], a);
        g_z1[h * N_PTS + row] = a;
        float v = a, v2 = a * a;
#pragma unroll
        for (int o = 16; o; o >>= 1) {
            v  += __shfl_down_sync(0xffffffffu, v,  o);
            v2 += __shfl_down_sync(0xffffffffu, v2, o);
        }
        if (lane == 0) { atomicAdd(&s_sum[h], v); atomicAdd(&s_sq[h], v2); }
    }
    __syncthreads();
    if (t < H_DIM) {
        atomicAdd(&g_bn[t], s_sum[t]);
        atomicAdd(&g_bn[H_DIM + t], s_sq[t]);
    }
}

// ---------------- MLP stage 2 ----------------
__global__ void k_mlp2(const float* __restrict__ W2,
                       const float* __restrict__ b2,
                       const float* __restrict__ g1,
                       const float* __restrict__ be1) {
    __shared__ float sW[H_DIM * H_DIM];
    __shared__ float s_mu[H_DIM], s_rs[H_DIM], s_g[H_DIM], s_be[H_DIM], s_b2[H_DIM];
    __shared__ float s_sum[H_DIM], s_sq[H_DIM];
    int t = threadIdx.x;
    for (int i = t; i < H_DIM * H_DIM; i += blockDim.x) sW[i] = W2[i];
    if (t < H_DIM) {
        float mu  = g_bn[t] * (1.0f / N_PTS);
        float var = g_bn[H_DIM + t] * (1.0f / N_PTS) - mu * mu;
        s_mu[t] = mu;
        s_rs[t] = rsqrtf(var + 1e-5f);
        s_g[t] = g1[t]; s_be[t] = be1[t]; s_b2[t] = b2[t];
        s_sum[t] = 0.0f; s_sq[t] = 0.0f;
    }
    __syncthreads();

    int row = blockIdx.x * blockDim.x + t;
    float h1[H_DIM];
#pragma unroll
    for (int h = 0; h < H_DIM; h++) {
        float x = g_z1[h * N_PTS + row];
        x = s_g[h] * (x - s_mu[h]) * s_rs[h] + s_be[h];
        h1[h] = gelu_exact(x);
    }

    int lane = t & 31;
    for (int j = 0; j < H_DIM; j++) {
        float acc = s_b2[j];
#pragma unroll
        for (int h = 0; h < H_DIM; h++) acc = fmaf(h1[h], sW[h * H_DIM + j], acc);
        g_z2[j * N_PTS + row] = acc;
        float v = acc, v2 = acc * acc;
#pragma unroll
        for (int o = 16; o; o >>= 1) {
            v  += __shfl_down_sync(0xffffffffu, v,  o);
            v2 += __shfl_down_sync(0xffffffffu, v2, o);
        }
        if (lane == 0) { atomicAdd(&s_sum[j], v); atomicAdd(&s_sq[j], v2); }
    }
    __syncthreads();
    if (t < H_DIM) {
        atomicAdd(&g_bn[2 * H_DIM + t], s_sum[t]);
        atomicAdd(&g_bn[3 * H_DIM + t], s_sq[t]);
    }
}

// ---------------- MLP stage 3 ----------------
__global__ void k_mlp3(const float* __restrict__ W3,
                       const float* __restrict__ b3,
                       const float* __restrict__ g2,
                       const float* __restrict__ be2) {
    __shared__ float s_mu[H_DIM], s_rs[H_DIM], s_g[H_DIM], s_be[H_DIM], s_w3[H_DIM];
    __shared__ float s_b3;
    int t = threadIdx.x;
    if (t < H_DIM) {
        float mu  = g_bn[2 * H_DIM + t] * (1.0f / N_PTS);
        float var = g_bn[3 * H_DIM + t] * (1.0f / N_PTS) - mu * mu;
        s_mu[t] = mu;
        s_rs[t] = rsqrtf(var + 1e-5f);
        s_g[t] = g2[t]; s_be[t] = be2[t]; s_w3[t] = W3[t];
    }
    if (t == 0) s_b3 = b3[0];
    __syncthreads();

    int row = blockIdx.x * blockDim.x + t;
    float acc = s_b3;
#pragma unroll
    for (int h = 0; h < H_DIM; h++) {
        float x = g_z2[h * N_PTS + row];
        x = s_g[h] * (x - s_mu[h]) * s_rs[h] + s_be[h];
        x = gelu_exact(x);
        acc = fmaf(x, s_w3[h], acc);
    }
    g_s[row] = 1.0f / (1.0f + expf(-acc));
}

// ---------------- KNN: 2 threads/query, in-block smem merge + fused loss ------
// v = ||c||^2 - 2 q.c = d2 - ||q||^2 : per-query monotone in d2 (reference's
// own selection formula). Exact diff-form d2 recomputed for near neighbors.
__global__ void __launch_bounds__(2 * QPB, 4)
k_knn(const float* __restrict__ coords) {
    __shared__ float4 sc[TILE];                  // 32 KB; merge lists alias it
    __shared__ float s_red[4 * 5];

    int t = threadIdx.x;
    int sub = t >> 6;            // warps 0-1: sub0, warps 2-3: sub1
    int ql  = t & (QPB - 1);     // local query 0..63
    int qi  = blockIdx.x * QPB + ql;
    int scene_base = qi & ~(M_PTS - 1);

    float qx = coords[qi * 3 + 0];
    float qy = coords[qi * 3 + 1];
    float qz = coords[qi * 3 + 2];
    float ax = -2.0f * qx, ay = -2.0f * qy, az = -2.0f * qz;

    float dist[KF];
    int   idx[KF];
#pragma unroll
    for (int k = 0; k < KF; k++) { dist[k] = FLT_MAX; idx[k] = 0; }

    float buf_d[CAP];
    int   buf_i[CAP];
    int   cnt = 0;
    float tau = FLT_MAX;
    bool  boot = true;
    int   soff = sub * HALF;     // this sub's half-tile offset

    for (int tile = 0; tile < M_PTS; tile += TILE) {
        for (int i = t; i < TILE; i += 2 * QPB) {
            int g = (scene_base + tile + i) * 3;
            float x = coords[g], y = coords[g + 1], z = coords[g + 2];
            sc[i] = make_float4(x, y, z, fmaf(x, x, fmaf(y, y, z * z)));
        }
        __syncthreads();

        for (int chunk = 0; chunk < HALF; chunk += 32) {
            int cbase = scene_base + tile + soff + chunk;
            if (boot) {
#pragma unroll
                for (int cc = 0; cc < 32; cc++) {
                    float4 p = sc[soff + cc];
                    float v = fmaf(ax, p.x, fmaf(ay, p.y, fmaf(az, p.z, p.w)));
                    insert32(dist, idx, v, cbase + cc);
                }
                boot = false;
                tau = dist[KF - 1];
            } else {
#pragma unroll
                for (int cc = 0; cc < 32; cc++) {
                    float4 p = sc[soff + chunk + cc];
                    float v = fmaf(ax, p.x, fmaf(ay, p.y, fmaf(az, p.z, p.w)));
                    if (v < tau) {
                        buf_d[cnt] = v;
                        buf_i[cnt] = cbase + cc;
                        cnt++;
                    }
                }
                if (__any_sync(0xffffffffu, cnt > CAP - 32)) {
                    for (int j = 0; j < cnt; j++) {
                        float cd = buf_d[j];
                        if (cd < dist[KF - 1]) insert32(dist, idx, cd, buf_i[j]);
                    }
                    cnt = 0;
                    tau = dist[KF - 1];
                }
            }
        }
        __syncthreads();
    }
    for (int j = 0; j < cnt; j++) {
        float cd = buf_d[j];
        if (cd < dist[KF - 1]) insert32(dist, idx, cd, buf_i[j]);
    }

    // ---- in-block merge: sub1 publishes its sorted list, sub0 merges ----
    float* s_mv = (float*)sc;                // QPB*32 floats = 8 KB
    int*   s_mi = (int*)(sc + 512);          // next 8 KB (float4*512 = 8KB off)
    __syncthreads();                          // tile buffer dead; safe to alias
    if (sub == 1) {
#pragma unroll
        for (int k = 0; k < KF; k++) {
            s_mv[ql * KF + k] = dist[k];
            s_mi[ql * KF + k] = idx[k];
        }
    }
    __syncthreads();

    float num = 0.0f, den = 0.0f, lp = 0.0f, ln_ = 0.0f, nm = 0.0f, sm = 0.0f;
    if (sub == 0) {
        for (int j = 0; j < KF; j++) {
            float v = s_mv[ql * KF + j];
            if (v >= dist[KF - 1]) break;     // sorted stream; dist[31] monotone
            insert32(dist, idx, v, s_mi[ql * KF + j]);
        }

        // ---- fused loss (exact diff-form d2 for near neighbors) ----
        float si = g_s[qi];
#pragma unroll
        for (int k = 0; k < KN; k++) {
            int j = idx[k];
            float sj = g_s[j];
            float ad = fabsf(si - sj);
            float dx = qx - coords[j * 3 + 0];
            float dy = qy - coords[j * 3 + 1];
            float dz = qz - coords[j * 3 + 2];
            float d2 = fmaf(dz, dz, fmaf(dy, dy, dx * dx));
            float d  = sqrtf(fmaxf(d2, 1e-24f));
            float w  = expf(-d * 10.0f);                   // 1 / T_LOC
            num = fmaf(w * ad, ad, num);
            den += w;
            float simp = 1.0f - ad;
            float sg = 1.0f / (1.0f + expf(-2.0f * simp)); // / T_CON
            lp += logf(sg + 1e-8f);
            if (k < KS) nm += sj;
        }
#pragma unroll
        for (int k = KN; k < KF; k++) {
            float sj = g_s[idx[k]];
            float ad = fabsf(si - sj);
            float simn = 1.0f - ad;
            float sg = 1.0f / (1.0f + expf(-2.0f * simn));
            ln_ += logf(1.0f - sg + 1e-8f);
        }
        nm *= (1.0f / KS);
        sm = (si - nm) * (si - nm);
    }

    int lane = t & 31, wid = t >> 5;
    float v0 = num, v1 = den, v2 = lp, v3 = ln_, v4 = sm;
#pragma unroll
    for (int o = 16; o; o >>= 1) {
        v0 += __shfl_down_sync(0xffffffffu, v0, o);
        v1 += __shfl_down_sync(0xffffffffu, v1, o);
        v2 += __shfl_down_sync(0xffffffffu, v2, o);
        v3 += __shfl_down_sync(0xffffffffu, v3, o);
        v4 += __shfl_down_sync(0xffffffffu, v4, o);
    }
    __syncthreads();                          // protect s_red alias timing
    if (lane == 0) {
        s_red[wid * 5 + 0] = v0; s_red[wid * 5 + 1] = v1;
        s_red[wid * 5 + 2] = v2; s_red[wid * 5 + 3] = v3;
        s_red[wid * 5 + 4] = v4;
    }
    __syncthreads();
    if (t == 0) {
        double a0 = 0, a1 = 0, a2 = 0, a3 = 0, a4 = 0;
#pragma unroll
        for (int w = 0; w < 4; w++) {
            a0 += (double)s_red[w * 5 + 0];
            a1 += (double)s_red[w * 5 + 1];
            a2 += (double)s_red[w * 5 + 2];
            a3 += (double)s_red[w * 5 + 3];
            a4 += (double)s_red[w * 5 + 4];
        }
        atomicAdd(&g_acc[0], a0);
        atomicAdd(&g_acc[1], a1);
        atomicAdd(&g_acc[2], a2);
        atomicAdd(&g_acc[3], a3);
        atomicAdd(&g_acc[4], a4);
    }
}

__global__ void k_fin(float* __restrict__ out) {
    if (threadIdx.x == 0) {
        double loc = g_acc[0] / fmax(g_acc[1], 1e-8);
        double inv = 1.0 / ((double)N_PTS * (double)KN);
        double pos = -g_acc[2] * inv;
        double neg = -g_acc[3] * inv;
        double sm  = g_acc[4] / (double)N_PTS;
        out[0] = (float)(loc + 0.5 * (pos + neg) + 0.2 * sm);
    }
}

// ---------------- launch ----------------
extern "C" void kernel_launch(void* const* d_in, const int* in_sizes, int n_in,
                              void* d_out, int out_size) {
    const float* feat   = (const float*)d_in[0];
    const float* coords = (const float*)d_in[1];
    const float* W1 = (const float*)d_in[2];
    const float* b1 = (const float*)d_in[3];
    const float* g1 = (const float*)d_in[4];
    const float* be1 = (const float*)d_in[5];
    const float* W2 = (const float*)d_in[6];
    const float* b2 = (const float*)d_in[7];
    const float* g2 = (const float*)d_in[8];
    const float* be2 = (const float*)d_in[9];
    const float* W3 = (const float*)d_in[10];
    const float* b3 = (const float*)d_in[11];
    float* out = (float*)d_out;

    k_zero<<<1, 256>>>();
    k_mlp1<<<N_PTS / 256, 256>>>(feat, W1, b1);
    k_mlp2<<<N_PTS / 256, 256>>>(W2, b2, g1, be1);
    k_mlp3<<<N_PTS / 256, 256>>>(W3, b3, g2, be2);
    k_knn<<<N_PTS / QPB, 2 * QPB>>>(coords);
    k_fin<<<1, 1>>>(out);
}

// round 12
// speedup vs baseline: 1.4356x; 1.4356x over previous
#include <cuda_runtime.h>
#include <math.h>
#include <float.h>

#define N_PTS 32768
#define C_IN 6
#define H_DIM 64
#define M_PTS 8192
#define KF 32
#define KN 16
#define KS 8
#define TILE 2048
#define QPB 8                   // queries (warps) per block
#define FULLMASK 0xffffffffu

// ---------------- scratch (no dynamic allocation allowed) ----------------
__device__ float  g_z1[N_PTS * H_DIM];
__device__ float  g_z2[N_PTS * H_DIM];
__device__ float  g_s[N_PTS];
__device__ float  g_bn[4 * H_DIM];
__device__ double g_acc[6];

__global__ void k_zero() {
    int t = threadIdx.x;
    if (t < 4 * H_DIM) g_bn[t] = 0.0f;
    if (t < 6) g_acc[t] = 0.0;
}

__device__ __forceinline__ float gelu_exact(float x) {
    return 0.5f * x * (1.0f + erff(x * 0.70710678118654752f));
}

// ---------------- MLP stage 1 ----------------
__global__ void k_mlp1(const float* __restrict__ feat,
                       const float* __restrict__ W1,
                       const float* __restrict__ b1) {
    __shared__ float sW[C_IN * H_DIM];
    __shared__ float sb[H_DIM];
    __shared__ float s_sum[H_DIM], s_sq[H_DIM];
    int t = threadIdx.x;
    for (int i = t; i < C_IN * H_DIM; i += blockDim.x) sW[i] = W1[i];
    if (t < H_DIM) { sb[t] = b1[t]; s_sum[t] = 0.0f; s_sq[t] = 0.0f; }
    __syncthreads();

    int row = blockIdx.x * blockDim.x + t;
    float f[C_IN];
#pragma unroll
    for (int c = 0; c < C_IN; c++) f[c] = feat[row * C_IN + c];

    int lane = t & 31;
#pragma unroll
    for (int h = 0; h < H_DIM; h++) {
        float a = sb[h];
#pragma unroll
        for (int c = 0; c < C_IN; c++) a = fmaf(f[c], sW[c * H_DIM + h], a);
        g_z1[h * N_PTS + row] = a;
        float v = a, v2 = a * a;
#pragma unroll
        for (int o = 16; o; o >>= 1) {
            v  += __shfl_down_sync(FULLMASK, v,  o);
            v2 += __shfl_down_sync(FULLMASK, v2, o);
        }
        if (lane == 0) { atomicAdd(&s_sum[h], v); atomicAdd(&s_sq[h], v2); }
    }
    __syncthreads();
    if (t < H_DIM) {
        atomicAdd(&g_bn[t], s_sum[t]);
        atomicAdd(&g_bn[H_DIM + t], s_sq[t]);
    }
}

// ---------------- MLP stage 2 ----------------
__global__ void k_mlp2(const float* __restrict__ W2,
                       const float* __restrict__ b2,
                       const float* __restrict__ g1,
                       const float* __restrict__ be1) {
    __shared__ float sW[H_DIM * H_DIM];
    __shared__ float s_mu[H_DIM], s_rs[H_DIM], s_g[H_DIM], s_be[H_DIM], s_b2[H_DIM];
    __shared__ float s_sum[H_DIM], s_sq[H_DIM];
    int t = threadIdx.x;
    for (int i = t; i < H_DIM * H_DIM; i += blockDim.x) sW[i] = W2[i];
    if (t < H_DIM) {
        float mu  = g_bn[t] * (1.0f / N_PTS);
        float var = g_bn[H_DIM + t] * (1.0f / N_PTS) - mu * mu;
        s_mu[t] = mu;
        s_rs[t] = rsqrtf(var + 1e-5f);
        s_g[t] = g1[t]; s_be[t] = be1[t]; s_b2[t] = b2[t];
        s_sum[t] = 0.0f; s_sq[t] = 0.0f;
    }
    __syncthreads();

    int row = blockIdx.x * blockDim.x + t;
    float h1[H_DIM];
#pragma unroll
    for (int h = 0; h < H_DIM; h++) {
        float x = g_z1[h * N_PTS + row];
        x = s_g[h] * (x - s_mu[h]) * s_rs[h] + s_be[h];
        h1[h] = gelu_exact(x);
    }

    int lane = t & 31;
    for (int j = 0; j < H_DIM; j++) {
        float acc = s_b2[j];
#pragma unroll
        for (int h = 0; h < H_DIM; h++) acc = fmaf(h1[h], sW[h * H_DIM + j], acc);
        g_z2[j * N_PTS + row] = acc;
        float v = acc, v2 = acc * acc;
#pragma unroll
        for (int o = 16; o; o >>= 1) {
            v  += __shfl_down_sync(FULLMASK, v,  o);
            v2 += __shfl_down_sync(FULLMASK, v2, o);
        }
        if (lane == 0) { atomicAdd(&s_sum[j], v); atomicAdd(&s_sq[j], v2); }
    }
    __syncthreads();
    if (t < H_DIM) {
        atomicAdd(&g_bn[2 * H_DIM + t], s_sum[t]);
        atomicAdd(&g_bn[3 * H_DIM + t], s_sq[t]);
    }
}

// ---------------- MLP stage 3 ----------------
__global__ void k_mlp3(const float* __restrict__ W3,
                       const float* __restrict__ b3,
                       const float* __restrict__ g2,
                       const float* __restrict__ be2) {
    __shared__ float s_mu[H_DIM], s_rs[H_DIM], s_g[H_DIM], s_be[H_DIM], s_w3[H_DIM];
    __shared__ float s_b3;
    int t = threadIdx.x;
    if (t < H_DIM) {
        float mu  = g_bn[2 * H_DIM + t] * (1.0f / N_PTS);
        float var = g_bn[3 * H_DIM + t] * (1.0f / N_PTS) - mu * mu;
        s_mu[t] = mu;
        s_rs[t] = rsqrtf(var + 1e-5f);
        s_g[t] = g2[t]; s_be[t] = be2[t]; s_w3[t] = W3[t];
    }
    if (t == 0) s_b3 = b3[0];
    __syncthreads();

    int row = blockIdx.x * blockDim.x + t;
    float acc = s_b3;
#pragma unroll
    for (int h = 0; h < H_DIM; h++) {
        float x = g_z2[h * N_PTS + row];
        x = s_g[h] * (x - s_mu[h]) * s_rs[h] + s_be[h];
        x = gelu_exact(x);
        acc = fmaf(x, s_w3[h], acc);
    }
    g_s[row] = 1.0f / (1.0f + expf(-acc));
}

// ---------------- KNN: warp per query, shuffle-held sorted top-32 -------------
// v = ||c||^2 - 2 q.c = d2 - ||q||^2 : per-query monotone in d2 (reference's
// own selection formula). List lives one element/lane, sorted ascending across
// lanes. All branches after the ballot are warp-uniform: zero divergence.
__global__ void __launch_bounds__(32 * QPB)
k_knn(const float* __restrict__ coords) {
    __shared__ float4 sc[TILE];          // 32 KB staged candidates
    __shared__ float s_red[QPB][5];

    int t = threadIdx.x;
    int lane = t & 31, w = t >> 5;
    int qi = blockIdx.x * QPB + w;       // QPB divides M_PTS: no scene straddle
    int scene_base = qi & ~(M_PTS - 1);

    float qx = coords[qi * 3 + 0];
    float qy = coords[qi * 3 + 1];
    float qz = coords[qi * 3 + 2];
    float ax = -2.0f * qx, ay = -2.0f * qy, az = -2.0f * qz;

    float key = FLT_MAX;                 // lane's slot of the sorted 32-list
    int   kid = 0;
    float tau = FLT_MAX;                 // = key at lane 31

    for (int tile = 0; tile < M_PTS; tile += TILE) {
        for (int i = t; i < TILE; i += 32 * QPB) {
            int g = (scene_base + tile + i) * 3;
            float x = coords[g], y = coords[g + 1], z = coords[g + 2];
            sc[i] = make_float4(x, y, z, fmaf(x, x, fmaf(y, y, z * z)));
        }
        __syncthreads();

        for (int step = 0; step < TILE; step += 32) {
            float4 p = sc[step + lane];
            float v = fmaf(ax, p.x, fmaf(ay, p.y, fmaf(az, p.z, p.w)));
            unsigned m = __ballot_sync(FULLMASK, v < tau);
            while (m) {                          // warp-uniform loop
                int src = __ffs(m) - 1;
                m &= m - 1;                      // LSB first => index order
                float cv = __shfl_sync(FULLMASK, v, src);
                if (cv < tau) {                  // uniform; tau may have moved
                    int ci = scene_base + tile + step + src;
                    unsigned le = __ballot_sync(FULLMASK, key <= cv);
                    int pos = __popc(le);        // stable: equals stay ahead
                    float upk = __shfl_up_sync(FULLMASK, key, 1);
                    int   upi = __shfl_up_sync(FULLMASK, kid, 1);
                    if (lane >= pos) {
                        key = (lane == pos) ? cv : upk;
                        kid = (lane == pos) ? ci : upi;
                    }
                    tau = __shfl_sync(FULLMASK, key, 31);
                }
            }
        }
        __syncthreads();
    }

    // ---- fused loss: neighbor k lives in lane k (sorted) ----
    float si = g_s[qi];
    int j = kid;
    float sj = g_s[j];
    float ad = fabsf(si - sj);
    float num = 0.0f, den = 0.0f, lp = 0.0f, ln_ = 0.0f, nm = 0.0f;

    if (lane < KN) {
        float dx = qx - coords[j * 3 + 0];
        float dy = qy - coords[j * 3 + 1];
        float dz = qz - coords[j * 3 + 2];
        float d2 = fmaf(dz, dz, fmaf(dy, dy, dx * dx));  // exact diff-form
        float d  = sqrtf(fmaxf(d2, 1e-24f));
        float wq = expf(-d * 10.0f);                     // 1 / T_LOC
        num = wq * ad * ad;
        den = wq;
        float sg = 1.0f / (1.0f + expf(-2.0f * (1.0f - ad))); // / T_CON
        lp = logf(sg + 1e-8f);
        if (lane < KS) nm = sj;
    } else {
        float sg = 1.0f / (1.0f + expf(-2.0f * (1.0f - ad)));
        ln_ = logf(1.0f - sg + 1e-8f);
    }

#pragma unroll
    for (int o = 16; o; o >>= 1) {
        num += __shfl_down_sync(FULLMASK, num, o);
        den += __shfl_down_sync(FULLMASK, den, o);
        lp  += __shfl_down_sync(FULLMASK, lp,  o);
        ln_ += __shfl_down_sync(FULLMASK, ln_, o);
        nm  += __shfl_down_sync(FULLMASK, nm,  o);
    }
    if (lane == 0) {
        nm *= (1.0f / KS);
        float sm = (si - nm) * (si - nm);
        s_red[w][0] = num; s_red[w][1] = den; s_red[w][2] = lp;
        s_red[w][3] = ln_; s_red[w][4] = sm;
    }
    __syncthreads();
    if (t == 0) {
        double a0 = 0, a1 = 0, a2 = 0, a3 = 0, a4 = 0;
#pragma unroll
        for (int v = 0; v < QPB; v++) {
            a0 += (double)s_red[v][0];
            a1 += (double)s_red[v][1];
            a2 += (double)s_red[v][2];
            a3 += (double)s_red[v][3];
            a4 += (double)s_red[v][4];
        }
        atomicAdd(&g_acc[0], a0);
        atomicAdd(&g_acc[1], a1);
        atomicAdd(&g_acc[2], a2);
        atomicAdd(&g_acc[3], a3);
        atomicAdd(&g_acc[4], a4);
    }
}

__global__ void k_fin(float* __restrict__ out) {
    if (threadIdx.x == 0) {
        double loc = g_acc[0] / fmax(g_acc[1], 1e-8);
        double inv = 1.0 / ((double)N_PTS * (double)KN);
        double pos = -g_acc[2] * inv;
        double neg = -g_acc[3] * inv;
        double sm  = g_acc[4] / (double)N_PTS;
        out[0] = (float)(loc + 0.5 * (pos + neg) + 0.2 * sm);
    }
}

// ---------------- launch ----------------
extern "C" void kernel_launch(void* const* d_in, const int* in_sizes, int n_in,
                              void* d_out, int out_size) {
    const float* feat   = (const float*)d_in[0];
    const float* coords = (const float*)d_in[1];
    const float* W1 = (const float*)d_in[2];
    const float* b1 = (const float*)d_in[3];
    const float* g1 = (const float*)d_in[4];
    const float* be1 = (const float*)d_in[5];
    const float* W2 = (const float*)d_in[6];
    const float* b2 = (const float*)d_in[7];
    const float* g2 = (const float*)d_in[8];
    const float* be2 = (const float*)d_in[9];
    const float* W3 = (const float*)d_in[10];
    const float* b3 = (const float*)d_in[11];
    float* out = (float*)d_out;

    k_zero<<<1, 256>>>();
    k_mlp1<<<N_PTS / 256, 256>>>(feat, W1, b1);
    k_mlp2<<<N_PTS / 256, 256>>>(W2, b2, g1, be1);
    k_mlp3<<<N_PTS / 256, 256>>>(W3, b3, g2, be2);
    k_knn<<<N_PTS / QPB, 32 * QPB>>>(coords);
    k_fin<<<1, 1>>>(out);
}

// round 13
// speedup vs baseline: 2.1265x; 1.4813x over previous
#include <cuda_runtime.h>
#include <math.h>
#include <float.h>

#define N_PTS 32768
#define C_IN 6
#define H_DIM 64
#define M_PTS 8192
#define KF 32
#define KN 16
#define KS 8
#define QPB 8
#define NB 8                    // bins per axis
#define BINW 0.25f
#define NBINS_SCENE (NB * NB * NB)
#define NBINS_TOT (4 * NBINS_SCENE)
#define FULLMASK 0xffffffffu

// ---------------- scratch (no dynamic allocation allowed) ----------------
__device__ float  g_z1[N_PTS * H_DIM];
__device__ float  g_z2[N_PTS * H_DIM];
__device__ float  g_s[N_PTS];
__device__ float  g_bn[4 * H_DIM];
__device__ double g_acc[6];
__device__ int    g_bcnt[NBINS_TOT];
__device__ int    g_bstart[NBINS_TOT];
__device__ int    g_bend[NBINS_TOT];
__device__ int    g_bcur[NBINS_TOT];
__device__ float4 g_bpts[N_PTS];     // bin-sorted (x,y,z,||c||^2)
__device__ int    g_bidx[N_PTS];     // original index

__global__ void k_zero() {
    int t = blockIdx.x * blockDim.x + threadIdx.x;
    if (t < 4 * H_DIM) g_bn[t] = 0.0f;
    if (t < 6) g_acc[t] = 0.0;
    if (t < NBINS_TOT) g_bcnt[t] = 0;
}

__device__ __forceinline__ float gelu_exact(float x) {
    return 0.5f * x * (1.0f + erff(x * 0.70710678118654752f));
}

__device__ __forceinline__ int bin_of(float v) {
    int b = (int)floorf((v + 1.0f) * 4.0f);
    return min(NB - 1, max(0, b));
}

// ---------------- binning build ----------------
__global__ void k_count(const float* __restrict__ coords) {
    int i = blockIdx.x * blockDim.x + threadIdx.x;
    float x = coords[i * 3], y = coords[i * 3 + 1], z = coords[i * 3 + 2];
    int bin = (i >> 13) * NBINS_SCENE + bin_of(z) * 64 + bin_of(y) * 8 + bin_of(x);
    atomicAdd(&g_bcnt[bin], 1);
}

__global__ void k_scan() {       // 1 block, 1024 threads, Hillis-Steele on 2048
    __shared__ int a[NBINS_TOT], b[NBINS_TOT];
    int t = threadIdx.x;
    a[t] = g_bcnt[t]; a[t + 1024] = g_bcnt[t + 1024];
    __syncthreads();
    int* src = a; int* dst = b;
    for (int off = 1; off < NBINS_TOT; off <<= 1) {
        for (int i = t; i < NBINS_TOT; i += 1024) {
            int v = src[i];
            if (i >= off) v += src[i - off];
            dst[i] = v;
        }
        __syncthreads();
        int* tmp = src; src = dst; dst = tmp;
    }
    for (int i = t; i < NBINS_TOT; i += 1024) {
        int inc = src[i], cnt = g_bcnt[i];
        g_bstart[i] = inc - cnt;
        g_bend[i]   = inc;
        g_bcur[i]   = inc - cnt;
    }
}

__global__ void k_scatter(const float* __restrict__ coords) {
    int i = blockIdx.x * blockDim.x + threadIdx.x;
    float x = coords[i * 3], y = coords[i * 3 + 1], z = coords[i * 3 + 2];
    int bin = (i >> 13) * NBINS_SCENE + bin_of(z) * 64 + bin_of(y) * 8 + bin_of(x);
    int pos = atomicAdd(&g_bcur[bin], 1);
    g_bpts[pos] = make_float4(x, y, z, fmaf(x, x, fmaf(y, y, z * z)));
    g_bidx[pos] = i;
}

// ---------------- MLP stage 1 ----------------
__global__ void k_mlp1(const float* __restrict__ feat,
                       const float* __restrict__ W1,
                       const float* __restrict__ b1) {
    __shared__ float sW[C_IN * H_DIM];
    __shared__ float sb[H_DIM];
    __shared__ float s_sum[H_DIM], s_sq[H_DIM];
    int t = threadIdx.x;
    for (int i = t; i < C_IN * H_DIM; i += blockDim.x) sW[i] = W1[i];
    if (t < H_DIM) { sb[t] = b1[t]; s_sum[t] = 0.0f; s_sq[t] = 0.0f; }
    __syncthreads();

    int row = blockIdx.x * blockDim.x + t;
    float f[C_IN];
#pragma unroll
    for (int c = 0; c < C_IN; c++) f[c] = feat[row * C_IN + c];

    int lane = t & 31;
#pragma unroll
    for (int h = 0; h < H_DIM; h++) {
        float a = sb[h];
#pragma unroll
        for (int c = 0; c < C_IN; c++) a = fmaf(f[c], sW[c * H_DIM + h], a);
        g_z1[h * N_PTS + row] = a;
        float v = a, v2 = a * a;
#pragma unroll
        for (int o = 16; o; o >>= 1) {
            v  += __shfl_down_sync(FULLMASK, v,  o);
            v2 += __shfl_down_sync(FULLMASK, v2, o);
        }
        if (lane == 0) { atomicAdd(&s_sum[h], v); atomicAdd(&s_sq[h], v2); }
    }
    __syncthreads();
    if (t < H_DIM) {
        atomicAdd(&g_bn[t], s_sum[t]);
        atomicAdd(&g_bn[H_DIM + t], s_sq[t]);
    }
}

// ---------------- MLP stage 2 ----------------
__global__ void k_mlp2(const float* __restrict__ W2,
                       const float* __restrict__ b2,
                       const float* __restrict__ g1,
                       const float* __restrict__ be1) {
    __shared__ float sW[H_DIM * H_DIM];
    __shared__ float s_mu[H_DIM], s_rs[H_DIM], s_g[H_DIM], s_be[H_DIM], s_b2[H_DIM];
    __shared__ float s_sum[H_DIM], s_sq[H_DIM];
    int t = threadIdx.x;
    for (int i = t; i < H_DIM * H_DIM; i += blockDim.x) sW[i] = W2[i];
    if (t < H_DIM) {
        float mu  = g_bn[t] * (1.0f / N_PTS);
        float var = g_bn[H_DIM + t] * (1.0f / N_PTS) - mu * mu;
        s_mu[t] = mu;
        s_rs[t] = rsqrtf(var + 1e-5f);
        s_g[t] = g1[t]; s_be[t] = be1[t]; s_b2[t] = b2[t];
        s_sum[t] = 0.0f; s_sq[t] = 0.0f;
    }
    __syncthreads();

    int row = blockIdx.x * blockDim.x + t;
    float h1[H_DIM];
#pragma unroll
    for (int h = 0; h < H_DIM; h++) {
        float x = g_z1[h * N_PTS + row];
        x = s_g[h] * (x - s_mu[h]) * s_rs[h] + s_be[h];
        h1[h] = gelu_exact(x);
    }

    int lane = t & 31;
    for (int j = 0; j < H_DIM; j++) {
        float acc = s_b2[j];
#pragma unroll
        for (int h = 0; h < H_DIM; h++) acc = fmaf(h1[h], sW[h * H_DIM + j], acc);
        g_z2[j * N_PTS + row] = acc;
        float v = acc, v2 = acc * acc;
#pragma unroll
        for (int o = 16; o; o >>= 1) {
            v  += __shfl_down_sync(FULLMASK, v,  o);
            v2 += __shfl_down_sync(FULLMASK, v2, o);
        }
        if (lane == 0) { atomicAdd(&s_sum[j], v); atomicAdd(&s_sq[j], v2); }
    }
    __syncthreads();
    if (t < H_DIM) {
        atomicAdd(&g_bn[2 * H_DIM + t], s_sum[t]);
        atomicAdd(&g_bn[3 * H_DIM + t], s_sq[t]);
    }
}

// ---------------- MLP stage 3 ----------------
__global__ void k_mlp3(const float* __restrict__ W3,
                       const float* __restrict__ b3,
                       const float* __restrict__ g2,
                       const float* __restrict__ be2) {
    __shared__ float s_mu[H_DIM], s_rs[H_DIM], s_g[H_DIM], s_be[H_DIM], s_w3[H_DIM];
    __shared__ float s_b3;
    int t = threadIdx.x;
    if (t < H_DIM) {
        float mu  = g_bn[2 * H_DIM + t] * (1.0f / N_PTS);
        float var = g_bn[3 * H_DIM + t] * (1.0f / N_PTS) - mu * mu;
        s_mu[t] = mu;
        s_rs[t] = rsqrtf(var + 1e-5f);
        s_g[t] = g2[t]; s_be[t] = be2[t]; s_w3[t] = W3[t];
    }
    if (t == 0) s_b3 = b3[0];
    __syncthreads();

    int row = blockIdx.x * blockDim.x + t;
    float acc = s_b3;
#pragma unroll
    for (int h = 0; h < H_DIM; h++) {
        float x = g_z2[h * N_PTS + row];
        x = s_g[h] * (x - s_mu[h]) * s_rs[h] + s_be[h];
        x = gelu_exact(x);
        acc = fmaf(x, s_w3[h], acc);
    }
    g_s[row] = 1.0f / (1.0f + expf(-acc));
}

// ---------------- KNN: warp per query, binned shell traversal -----------------
// v = ||c||^2 - 2 q.c = d2 - ||q||^2 (reference's selection formula). Sorted
// top-32 lives one element/lane. Shell termination is exact: stop when even
// the closest possible point of the next shell exceeds tau (+fp safety).
__global__ void __launch_bounds__(32 * QPB)
k_knn(const float* __restrict__ coords) {
    __shared__ float s_red[QPB][5];

    int t = threadIdx.x;
    int lane = t & 31, w = t >> 5;
    int qi = blockIdx.x * QPB + w;
    int scene = qi >> 13;
    int sbase_bins = scene * NBINS_SCENE;

    float qx = coords[qi * 3 + 0];
    float qy = coords[qi * 3 + 1];
    float qz = coords[qi * 3 + 2];
    float qn = fmaf(qx, qx, fmaf(qy, qy, qz * qz));
    float ax = -2.0f * qx, ay = -2.0f * qy, az = -2.0f * qz;

    int bx = bin_of(qx), by = bin_of(qy), bz = bin_of(qz);
    // min margin from q to any face of its home bin
    float lx = qx - (-1.0f + bx * BINW), rx = BINW - lx;
    float ly = qy - (-1.0f + by * BINW), ry = BINW - ly;
    float lz = qz - (-1.0f + bz * BINW), rz = BINW - lz;
    float mar = fminf(fminf(fminf(lx, rx), fminf(ly, ry)), fminf(lz, rz));
    mar = fmaxf(mar, 0.0f);

    float key = FLT_MAX;
    int   kid = 0;
    float tau = FLT_MAX;

    for (int sig = 0; sig < NB; sig++) {
        if (sig > 0) {
            float dmin = (sig - 1) * BINW + mar;
            float d2tau = tau + qn + 1e-4f;      // v-space -> d2-space + safety
            if (dmin * dmin > d2tau) break;
        }
        for (int dz = -sig; dz <= sig; dz++) {
            int cz = bz + dz;
            if (cz < 0 || cz >= NB) continue;
            for (int dy = -sig; dy <= sig; dy++) {
                int cy = by + dy;
                if (cy < 0 || cy >= NB) continue;
                bool full = (abs(dz) == sig) || (abs(dy) == sig);
                int step = full ? 1 : 2 * sig;
                for (int dx = -sig; dx <= sig; dx += step) {
                    int cx = bx + dx;
                    if (cx < 0 || cx >= NB) continue;
                    int bin = sbase_bins + cz * 64 + cy * 8 + cx;
                    int st = g_bstart[bin], en = g_bend[bin];
                    for (int c = st; c < en; c += 32) {
                        int i = c + lane;
                        float v = FLT_MAX;
                        if (i < en) {
                            float4 p = g_bpts[i];
                            v = fmaf(ax, p.x, fmaf(ay, p.y, fmaf(az, p.z, p.w)));
                        }
                        unsigned m = __ballot_sync(FULLMASK, v < tau);
                        while (m) {                       // warp-uniform
                            int src = __ffs(m) - 1;
                            m &= m - 1;
                            float cv = __shfl_sync(FULLMASK, v, src);
                            if (cv < tau) {
                                int ci = g_bidx[c + src];
                                unsigned le = __ballot_sync(FULLMASK, key <= cv);
                                int pos = __popc(le);
                                float upk = __shfl_up_sync(FULLMASK, key, 1);
                                int   upi = __shfl_up_sync(FULLMASK, kid, 1);
                                if (lane >= pos) {
                                    key = (lane == pos) ? cv : upk;
                                    kid = (lane == pos) ? ci : upi;
                                }
                                tau = __shfl_sync(FULLMASK, key, 31);
                            }
                        }
                    }
                }
            }
        }
    }

    // ---- fused loss: neighbor k lives in lane k (sorted) ----
    float si = g_s[qi];
    int j = kid;
    float sj = g_s[j];
    float ad = fabsf(si - sj);
    float num = 0.0f, den = 0.0f, lp = 0.0f, ln_ = 0.0f, nm = 0.0f;

    if (lane < KN) {
        float dx = qx - coords[j * 3 + 0];
        float dy = qy - coords[j * 3 + 1];
        float dz = qz - coords[j * 3 + 2];
        float d2 = fmaf(dz, dz, fmaf(dy, dy, dx * dx));   // exact diff-form
        float d  = sqrtf(fmaxf(d2, 1e-24f));
        float wq = expf(-d * 10.0f);                      // 1 / T_LOC
        num = wq * ad * ad;
        den = wq;
        float sg = 1.0f / (1.0f + expf(-2.0f * (1.0f - ad))); // / T_CON
        lp = logf(sg + 1e-8f);
        if (lane < KS) nm = sj;
    } else {
        float sg = 1.0f / (1.0f + expf(-2.0f * (1.0f - ad)));
        ln_ = logf(1.0f - sg + 1e-8f);
    }

#pragma unroll
    for (int o = 16; o; o >>= 1) {
        num += __shfl_down_sync(FULLMASK, num, o);
        den += __shfl_down_sync(FULLMASK, den, o);
        lp  += __shfl_down_sync(FULLMASK, lp,  o);
        ln_ += __shfl_down_sync(FULLMASK, ln_, o);
        nm  += __shfl_down_sync(FULLMASK, nm,  o);
    }
    if (lane == 0) {
        nm *= (1.0f / KS);
        float sm = (si - nm) * (si - nm);
        s_red[w][0] = num; s_red[w][1] = den; s_red[w][2] = lp;
        s_red[w][3] = ln_; s_red[w][4] = sm;
    }
    __syncthreads();
    if (t == 0) {
        double a0 = 0, a1 = 0, a2 = 0, a3 = 0, a4 = 0;
#pragma unroll
        for (int v = 0; v < QPB; v++) {
            a0 += (double)s_red[v][0];
            a1 += (double)s_red[v][1];
            a2 += (double)s_red[v][2];
            a3 += (double)s_red[v][3];
            a4 += (double)s_red[v][4];
        }
        atomicAdd(&g_acc[0], a0);
        atomicAdd(&g_acc[1], a1);
        atomicAdd(&g_acc[2], a2);
        atomicAdd(&g_acc[3], a3);
        atomicAdd(&g_acc[4], a4);
    }
}

__global__ void k_fin(float* __restrict__ out) {
    if (threadIdx.x == 0) {
        double loc = g_acc[0] / fmax(g_acc[1], 1e-8);
        double inv = 1.0 / ((double)N_PTS * (double)KN);
        double pos = -g_acc[2] * inv;
        double neg = -g_acc[3] * inv;
        double sm  = g_acc[4] / (double)N_PTS;
        out[0] = (float)(loc + 0.5 * (pos + neg) + 0.2 * sm);
    }
}

// ---------------- launch ----------------
extern "C" void kernel_launch(void* const* d_in, const int* in_sizes, int n_in,
                              void* d_out, int out_size) {
    const float* feat   = (const float*)d_in[0];
    const float* coords = (const float*)d_in[1];
    const float* W1 = (const float*)d_in[2];
    const float* b1 = (const float*)d_in[3];
    const float* g1 = (const float*)d_in[4];
    const float* be1 = (const float*)d_in[5];
    const float* W2 = (const float*)d_in[6];
    const float* b2 = (const float*)d_in[7];
    const float* g2 = (const float*)d_in[8];
    const float* be2 = (const float*)d_in[9];
    const float* W3 = (const float*)d_in[10];
    const float* b3 = (const float*)d_in[11];
    float* out = (float*)d_out;

    k_zero<<<8, 256>>>();
    k_count<<<N_PTS / 256, 256>>>(coords);
    k_scan<<<1, 1024>>>();
    k_scatter<<<N_PTS / 256, 256>>>(coords);
    k_mlp1<<<N_PTS / 256, 256>>>(feat, W1, b1);
    k_mlp2<<<N_PTS / 256, 256>>>(W2, b2, g1, be1);
    k_mlp3<<<N_PTS / 256, 256>>>(W3, b3, g2, be2);
    k_knn<<<N_PTS / QPB, 32 * QPB>>>(coords);
    k_fin<<<1, 1>>>(out);
}

// round 16
// speedup vs baseline: 2.1433x; 1.0079x over previous
#include <cuda_runtime.h>
#include <math.h>
#include <float.h>

#define N_PTS 32768
#define C_IN 6
#define H_DIM 64
#define M_PTS 8192
#define KF 32
#define KN 16
#define KS 8
#define QPB 8
#define NB 8
#define BINW 0.25f
#define NBINS_SCENE (NB * NB * NB)
#define NBINS_TOT (4 * NBINS_SCENE)
#define FULLMASK 0xffffffffu

// ---------------- scratch ----------------
__device__ float  g_z1[N_PTS * H_DIM];
__device__ float  g_z2[N_PTS * H_DIM];
__device__ float  g_s[N_PTS];
__device__ float  g_bn[4 * H_DIM];
__device__ double g_acc[6];
__device__ int    g_bcnt[NBINS_TOT];
__device__ int    g_bstart[NBINS_TOT];
__device__ int    g_bend[NBINS_TOT];
__device__ int    g_bcur[NBINS_TOT];
__device__ float4 g_bpts[N_PTS];
__device__ int    g_bidx[N_PTS];

__global__ void k_zero() {
    int t = blockIdx.x * blockDim.x + threadIdx.x;
    if (t < 4 * H_DIM) g_bn[t] = 0.0f;
    if (t < 6) g_acc[t] = 0.0;
    if (t < NBINS_TOT) g_bcnt[t] = 0;
}

__device__ __forceinline__ float gelu_exact(float x) {
    return 0.5f * x * (1.0f + erff(x * 0.70710678118654752f));
}

__device__ __forceinline__ int bin_of(float v) {
    int b = (int)floorf((v + 1.0f) * 4.0f);
    return min(NB - 1, max(0, b));
}

// ---------------- binning build ----------------
__global__ void k_count(const float* __restrict__ coords) {
    int i = blockIdx.x * blockDim.x + threadIdx.x;
    float x = coords[i * 3], y = coords[i * 3 + 1], z = coords[i * 3 + 2];
    int bin = (i >> 13) * NBINS_SCENE + bin_of(z) * 64 + bin_of(y) * 8 + bin_of(x);
    atomicAdd(&g_bcnt[bin], 1);
}

// 2-level warp-shuffle scan over 2048 bins (1024 threads, 2 bins/thread)
__global__ void k_scan() {
    __shared__ int wsum[32], woff[32];
    int t = threadIdx.x, lane = t & 31, wid = t >> 5;
    int v0 = g_bcnt[2 * t], v1 = g_bcnt[2 * t + 1];
    int s = v0 + v1;
    int sc = s;
#pragma unroll
    for (int o = 1; o < 32; o <<= 1) {
        int u = __shfl_up_sync(FULLMASK, sc, o);
        if (lane >= o) sc += u;
    }
    if (lane == 31) wsum[wid] = sc;
    __syncthreads();
    if (wid == 0) {
        int w = wsum[lane];
#pragma unroll
        for (int o = 1; o < 32; o <<= 1) {
            int u = __shfl_up_sync(FULLMASK, w, o);
            if (lane >= o) w += u;
        }
        woff[lane] = w;
    }
    __syncthreads();
    int base = (wid > 0 ? woff[wid - 1] : 0) + sc - s;   // exclusive prefix
    g_bstart[2 * t] = base;       g_bend[2 * t] = base + v0;       g_bcur[2 * t] = base;
    g_bstart[2 * t + 1] = base + v0; g_bend[2 * t + 1] = base + v0 + v1; g_bcur[2 * t + 1] = base + v0;
}

__global__ void k_scatter(const float* __restrict__ coords) {
    int i = blockIdx.x * blockDim.x + threadIdx.x;
    float x = coords[i * 3], y = coords[i * 3 + 1], z = coords[i * 3 + 2];
    int bin = (i >> 13) * NBINS_SCENE + bin_of(z) * 64 + bin_of(y) * 8 + bin_of(x);
    int pos = atomicAdd(&g_bcur[bin], 1);
    g_bpts[pos] = make_float4(x, y, z, fmaf(x, x, fmaf(y, y, z * z)));
    g_bidx[pos] = i;
}

// ---------------- MLP stage 1 ----------------
__global__ void k_mlp1(const float* __restrict__ feat,
                       const float* __restrict__ W1,
                       const float* __restrict__ b1) {
    __shared__ float sW[C_IN * H_DIM];
    __shared__ float sb[H_DIM];
    __shared__ float s_sum[H_DIM], s_sq[H_DIM];
    int t = threadIdx.x;
    for (int i = t; i < C_IN * H_DIM; i += blockDim.x) sW[i] = W1[i];
    if (t < H_DIM) { sb[t] = b1[t]; s_sum[t] = 0.0f; s_sq[t] = 0.0f; }
    __syncthreads();

    int row = blockIdx.x * blockDim.x + t;
    float f[C_IN];
#pragma unroll
    for (int c = 0; c < C_IN; c++) f[c] = feat[row * C_IN + c];

    int lane = t & 31;
#pragma unroll
    for (int h = 0; h < H_DIM; h++) {
        float a = sb[h];
#pragma unroll
        for (int c = 0; c < C_IN; c++) a = fmaf(f[c], sW[c * H_DIM + h], a);
        g_z1[h * N_PTS + row] = a;
        float v = a, v2 = a * a;
#pragma unroll
        for (int o = 16; o; o >>= 1) {
            v  += __shfl_down_sync(FULLMASK, v,  o);
            v2 += __shfl_down_sync(FULLMASK, v2, o);
        }
        if (lane == 0) { atomicAdd(&s_sum[h], v); atomicAdd(&s_sq[h], v2); }
    }
    __syncthreads();
    if (t < H_DIM) {
        atomicAdd(&g_bn[t], s_sum[t]);
        atomicAdd(&g_bn[H_DIM + t], s_sq[t]);
    }
}

// ---------------- MLP stage 2: 2 threads per row ----------------
#define M2_ROWS 128
__global__ void k_mlp2(const float* __restrict__ W2,
                       const float* __restrict__ b2,
                       const float* __restrict__ g1,
                       const float* __restrict__ be1) {
    __shared__ float sW[H_DIM * H_DIM];
    __shared__ float s_mu[H_DIM], s_rs[H_DIM], s_g[H_DIM], s_be[H_DIM], s_b2[H_DIM];
    __shared__ float s_sum[H_DIM], s_sq[H_DIM];
    int t = threadIdx.x;
    for (int i = t; i < H_DIM * H_DIM; i += blockDim.x) sW[i] = W2[i];
    if (t < H_DIM) {
        float mu  = g_bn[t] * (1.0f / N_PTS);
        float var = g_bn[H_DIM + t] * (1.0f / N_PTS) - mu * mu;
        s_mu[t] = mu;
        s_rs[t] = rsqrtf(var + 1e-5f);
        s_g[t] = g1[t]; s_be[t] = be1[t]; s_b2[t] = b2[t];
        s_sum[t] = 0.0f; s_sq[t] = 0.0f;
    }
    __syncthreads();

    int half = t >> 7;                    // 0 or 1
    int r    = t & (M2_ROWS - 1);
    int row  = blockIdx.x * M2_ROWS + r;

    float h1[H_DIM];
#pragma unroll
    for (int h = 0; h < H_DIM; h++) {
        float x = g_z1[h * N_PTS + row];
        x = s_g[h] * (x - s_mu[h]) * s_rs[h] + s_be[h];
        h1[h] = gelu_exact(x);
    }

    int lane = t & 31;
    int j0 = half * 32;
    for (int jj = 0; jj < 32; jj++) {
        int j = j0 + jj;
        float acc = s_b2[j];
#pragma unroll
        for (int h = 0; h < H_DIM; h++) acc = fmaf(h1[h], sW[h * H_DIM + j], acc);
        g_z2[j * N_PTS + row] = acc;
        float v = acc, v2 = acc * acc;
#pragma unroll
        for (int o = 16; o; o >>= 1) {
            v  += __shfl_down_sync(FULLMASK, v,  o);
            v2 += __shfl_down_sync(FULLMASK, v2, o);
        }
        if (lane == 0) { atomicAdd(&s_sum[j], v); atomicAdd(&s_sq[j], v2); }
    }
    __syncthreads();
    if (t < H_DIM) {
        atomicAdd(&g_bn[2 * H_DIM + t], s_sum[t]);
        atomicAdd(&g_bn[3 * H_DIM + t], s_sq[t]);
    }
}

// ---------------- MLP stage 3 ----------------
__global__ void k_mlp3(const float* __restrict__ W3,
                       const float* __restrict__ b3,
                       const float* __restrict__ g2,
                       const float* __restrict__ be2) {
    __shared__ float s_mu[H_DIM], s_rs[H_DIM], s_g[H_DIM], s_be[H_DIM], s_w3[H_DIM];
    __shared__ float s_b3;
    int t = threadIdx.x;
    if (t < H_DIM) {
        float mu  = g_bn[2 * H_DIM + t] * (1.0f / N_PTS);
        float var = g_bn[3 * H_DIM + t] * (1.0f / N_PTS) - mu * mu;
        s_mu[t] = mu;
        s_rs[t] = rsqrtf(var + 1e-5f);
        s_g[t] = g2[t]; s_be[t] = be2[t]; s_w3[t] = W3[t];
    }
    if (t == 0) s_b3 = b3[0];
    __syncthreads();

    int row = blockIdx.x * blockDim.x + t;
    float acc = s_b3;
#pragma unroll
    for (int h = 0; h < H_DIM; h++) {
        float x = g_z2[h * N_PTS + row];
        x = s_g[h] * (x - s_mu[h]) * s_rs[h] + s_be[h];
        x = gelu_exact(x);
        acc = fmaf(x, s_w3[h], acc);
    }
    g_s[row] = 1.0f / (1.0f + expf(-acc));
}

// ---------------- KNN: warp/query, row-contiguous binned shells ---------------
__device__ __forceinline__ void scan_range(
    int st, int en, int lane,
    float ax, float ay, float az,
    float& key, int& kid, float& tau
) {
    for (int c = st; c < en; c += 32) {
        int i = c + lane;
        float v = FLT_MAX;
        if (i < en) {
            float4 p = g_bpts[i];
            v = fmaf(ax, p.x, fmaf(ay, p.y, fmaf(az, p.z, p.w)));
        }
        unsigned m = __ballot_sync(FULLMASK, v < tau);
        while (m) {                           // warp-uniform
            int src = __ffs(m) - 1;
            m &= m - 1;                       // LSB first => index order
            float cv = __shfl_sync(FULLMASK, v, src);
            if (cv < tau) {
                int ci = g_bidx[c + src];
                unsigned le = __ballot_sync(FULLMASK, key <= cv);
                int pos = __popc(le);         // stable: equals stay ahead
                float upk = __shfl_up_sync(FULLMASK, key, 1);
                int   upi = __shfl_up_sync(FULLMASK, kid, 1);
                if (lane >= pos) {
                    key = (lane == pos) ? cv : upk;
                    kid = (lane == pos) ? ci : upi;
                }
                tau = __shfl_sync(FULLMASK, key, 31);
            }
        }
    }
}

__global__ void __launch_bounds__(32 * QPB)
k_knn(const float* __restrict__ coords) {
    __shared__ float s_red[QPB][5];

    int t = threadIdx.x;
    int lane = t & 31, w = t >> 5;
    int qi = blockIdx.x * QPB + w;
    int sbase_bins = (qi >> 13) * NBINS_SCENE;

    float qx = coords[qi * 3 + 0];
    float qy = coords[qi * 3 + 1];
    float qz = coords[qi * 3 + 2];
    float qn = fmaf(qx, qx, fmaf(qy, qy, qz * qz));
    float ax = -2.0f * qx, ay = -2.0f * qy, az = -2.0f * qz;

    int bx = bin_of(qx), by = bin_of(qy), bz = bin_of(qz);
    float lx = qx - (-1.0f + bx * BINW), rx = BINW - lx;
    float ly = qy - (-1.0f + by * BINW), ry = BINW - ly;
    float lz = qz - (-1.0f + bz * BINW), rz = BINW - lz;
    float mar = fmaxf(fminf(fminf(fminf(lx, rx), fminf(ly, ry)), fminf(lz, rz)), 0.0f);

    float key = FLT_MAX;
    int   kid = 0;
    float tau = FLT_MAX;

    // Phase A: 3x3x3 cube (shells 0+1), each (z,y) row contiguous in x
    {
        int z0 = max(0, bz - 1), z1 = min(NB - 1, bz + 1);
        int y0 = max(0, by - 1), y1 = min(NB - 1, by + 1);
        int x0 = max(0, bx - 1), x1 = min(NB - 1, bx + 1);
        for (int cz = z0; cz <= z1; cz++)
            for (int cy = y0; cy <= y1; cy++) {
                int rowb = sbase_bins + cz * 64 + cy * 8;
                scan_range(g_bstart[rowb + x0], g_bend[rowb + x1],
                           lane, ax, ay, az, key, kid, tau);
            }
    }

    // Phase B: shells sigma >= 2 with exact termination
    for (int sig = 2; sig < NB; sig++) {
        float dmin = (sig - 1) * BINW + mar;
        float d2tau = tau + qn + 1e-4f;          // v-space -> d2-space + fp safety
        if (dmin * dmin > d2tau) break;
        for (int dz = -sig; dz <= sig; dz++) {
            int cz = bz + dz;
            if (cz < 0 || cz >= NB) continue;
            for (int dy = -sig; dy <= sig; dy++) {
                int cy = by + dy;
                if (cy < 0 || cy >= NB) continue;
                int rowb = sbase_bins + cz * 64 + cy * 8;
                if (abs(dz) == sig || abs(dy) == sig) {
                    int x0 = max(0, bx - sig), x1 = min(NB - 1, bx + sig);
                    scan_range(g_bstart[rowb + x0], g_bend[rowb + x1],
                               lane, ax, ay, az, key, kid, tau);
                } else {
                    int cxl = bx - sig, cxr = bx + sig;
                    if (cxl >= 0)
                        scan_range(g_bstart[rowb + cxl], g_bend[rowb + cxl],
                                   lane, ax, ay, az, key, kid, tau);
                    if (cxr < NB)
                        scan_range(g_bstart[rowb + cxr], g_bend[rowb + cxr],
                                   lane, ax, ay, az, key, kid, tau);
                }
            }
        }
    }

    // ---- fused loss: neighbor k lives in lane k (sorted) ----
    float si = g_s[qi];
    int j = kid;
    float sj = g_s[j];
    float ad = fabsf(si - sj);
    float num = 0.0f, den = 0.0f, lp = 0.0f, ln_ = 0.0f, nm = 0.0f;

    if (lane < KN) {
        float dx = qx - coords[j * 3 + 0];
        float dy = qy - coords[j * 3 + 1];
        float dz = qz - coords[j * 3 + 2];
        float d2 = fmaf(dz, dz, fmaf(dy, dy, dx * dx));
        float d  = sqrtf(fmaxf(d2, 1e-24f));
        float wq = expf(-d * 10.0f);
        num = wq * ad * ad;
        den = wq;
        float sg = 1.0f / (1.0f + expf(-2.0f * (1.0f - ad)));
        lp = logf(sg + 1e-8f);
        if (lane < KS) nm = sj;
    } else {
        float sg = 1.0f / (1.0f + expf(-2.0f * (1.0f - ad)));
        ln_ = logf(1.0f - sg + 1e-8f);
    }

#pragma unroll
    for (int o = 16; o; o >>= 1) {
        num += __shfl_down_sync(FULLMASK, num, o);
        den += __shfl_down_sync(FULLMASK, den, o);
        lp  += __shfl_down_sync(FULLMASK, lp,  o);
        ln_ += __shfl_down_sync(FULLMASK, ln_, o);
        nm  += __shfl_down_sync(FULLMASK, nm,  o);
    }
    if (lane == 0) {
        nm *= (1.0f / KS);
        float sm = (si - nm) * (si - nm);
        s_red[w][0] = num; s_red[w][1] = den; s_red[w][2] = lp;
        s_red[w][3] = ln_; s_red[w][4] = sm;
    }
    __syncthreads();
    if (t == 0) {
        double a0 = 0, a1 = 0, a2 = 0, a3 = 0, a4 = 0;
#pragma unroll
        for (int v = 0; v < QPB; v++) {
            a0 += (double)s_red[v][0];
            a1 += (double)s_red[v][1];
            a2 += (double)s_red[v][2];
            a3 += (double)s_red[v][3];
            a4 += (double)s_red[v][4];
        }
        atomicAdd(&g_acc[0], a0);
        atomicAdd(&g_acc[1], a1);
        atomicAdd(&g_acc[2], a2);
        atomicAdd(&g_acc[3], a3);
        atomicAdd(&g_acc[4], a4);
    }
}

__global__ void k_fin(float* __restrict__ out) {
    if (threadIdx.x == 0) {
        double loc = g_acc[0] / fmax(g_acc[1], 1e-8);
        double inv = 1.0 / ((double)N_PTS * (double)KN);
        double pos = -g_acc[2] * inv;
        double neg = -g_acc[3] * inv;
        double sm  = g_acc[4] / (double)N_PTS;
        out[0] = (float)(loc + 0.5 * (pos + neg) + 0.2 * sm);
    }
}

// ---------------- launch ----------------
extern "C" void kernel_launch(void* const* d_in, const int* in_sizes, int n_in,
                              void* d_out, int out_size) {
    const float* feat   = (const float*)d_in[0];
    const float* coords = (const float*)d_in[1];
    const float* W1 = (const float*)d_in[2];
    const float* b1 = (const float*)d_in[3];
    const float* g1 = (const float*)d_in[4];
    const float* be1 = (const float*)d_in[5];
    const float* W2 = (const float*)d_in[6];
    const float* b2 = (const float*)d_in[7];
    const float* g2 = (const float*)d_in[8];
    const float* be2 = (const float*)d_in[9];
    const float* W3 = (const float*)d_in[10];
    const float* b3 = (const float*)d_in[11];
    float* out = (float*)d_out;

    k_zero<<<8, 256>>>();
    k_count<<<N_PTS / 256, 256>>>(coords);
    k_scan<<<1, 1024>>>();
    k_scatter<<<N_PTS / 256, 256>>>(coords);
    k_mlp1<<<N_PTS / 256, 256>>>(feat, W1, b1);
    k_mlp2<<<N_PTS / M2_ROWS, 256>>>(W2, b2, g1, be1);
    k_mlp3<<<N_PTS / 256, 256>>>(W3, b3, g2, be2);
    k_knn<<<N_PTS / QPB, 32 * QPB>>>(coords);
    k_fin<<<1, 1>>>(out);
}

// round 17
// speedup vs baseline: 2.9168x; 1.3609x over previous
#include <cuda_runtime.h>
#include <math.h>
#include <float.h>

#define N_PTS 32768
#define C_IN 6
#define H_DIM 64
#define M_PTS 8192
#define KF 32
#define KN 16
#define KS 8
#define QPB 8
#define NB 8
#define BINW 0.25f
#define NBINS_SCENE (NB * NB * NB)
#define NBINS_TOT (4 * NBINS_SCENE)
#define FULLMASK 0xffffffffu

// ---------------- scratch ----------------
__device__ float  g_z1[N_PTS * H_DIM];
__device__ float  g_z2[N_PTS * H_DIM];
__device__ float  g_s[N_PTS];
__device__ float  g_bn[4 * H_DIM];
__device__ double g_acc[6];
__device__ int    g_bcnt[NBINS_TOT];
__device__ int    g_bstart[NBINS_TOT];
__device__ int    g_bend[NBINS_TOT];
__device__ int    g_bcur[NBINS_TOT];
__device__ float4 g_bpts[N_PTS];
__device__ int    g_bidx[N_PTS];

__global__ void k_zero() {
    int t = blockIdx.x * blockDim.x + threadIdx.x;
    if (t < 4 * H_DIM) g_bn[t] = 0.0f;
    if (t < 6) g_acc[t] = 0.0;
    if (t < NBINS_TOT) g_bcnt[t] = 0;
}

__device__ __forceinline__ float gelu_exact(float x) {
    return 0.5f * x * (1.0f + erff(x * 0.70710678118654752f));
}

__device__ __forceinline__ int bin_of(float v) {
    int b = (int)floorf((v + 1.0f) * 4.0f);
    return min(NB - 1, max(0, b));
}

// ---------------- binning build ----------------
__global__ void k_count(const float* __restrict__ coords) {
    int i = blockIdx.x * blockDim.x + threadIdx.x;
    float x = coords[i * 3], y = coords[i * 3 + 1], z = coords[i * 3 + 2];
    int bin = (i >> 13) * NBINS_SCENE + bin_of(z) * 64 + bin_of(y) * 8 + bin_of(x);
    atomicAdd(&g_bcnt[bin], 1);
}

__global__ void k_scan() {
    __shared__ int wsum[32], woff[32];
    int t = threadIdx.x, lane = t & 31, wid = t >> 5;
    int v0 = g_bcnt[2 * t], v1 = g_bcnt[2 * t + 1];
    int s = v0 + v1;
    int sc = s;
#pragma unroll
    for (int o = 1; o < 32; o <<= 1) {
        int u = __shfl_up_sync(FULLMASK, sc, o);
        if (lane >= o) sc += u;
    }
    if (lane == 31) wsum[wid] = sc;
    __syncthreads();
    if (wid == 0) {
        int w = wsum[lane];
#pragma unroll
        for (int o = 1; o < 32; o <<= 1) {
            int u = __shfl_up_sync(FULLMASK, w, o);
            if (lane >= o) w += u;
        }
        woff[lane] = w;
    }
    __syncthreads();
    int base = (wid > 0 ? woff[wid - 1] : 0) + sc - s;
    g_bstart[2 * t] = base;       g_bend[2 * t] = base + v0;       g_bcur[2 * t] = base;
    g_bstart[2 * t + 1] = base + v0; g_bend[2 * t + 1] = base + v0 + v1; g_bcur[2 * t + 1] = base + v0;
}

__global__ void k_scatter(const float* __restrict__ coords) {
    int i = blockIdx.x * blockDim.x + threadIdx.x;
    float x = coords[i * 3], y = coords[i * 3 + 1], z = coords[i * 3 + 2];
    int bin = (i >> 13) * NBINS_SCENE + bin_of(z) * 64 + bin_of(y) * 8 + bin_of(x);
    int pos = atomicAdd(&g_bcur[bin], 1);
    g_bpts[pos] = make_float4(x, y, z, fmaf(x, x, fmaf(y, y, z * z)));
    g_bidx[pos] = i;
}

// ---------------- MLP stage 1 ----------------
__global__ void k_mlp1(const float* __restrict__ feat,
                       const float* __restrict__ W1,
                       const float* __restrict__ b1) {
    __shared__ float sW[C_IN * H_DIM];
    __shared__ float sb[H_DIM];
    __shared__ float s_sum[H_DIM], s_sq[H_DIM];
    int t = threadIdx.x;
    for (int i = t; i < C_IN * H_DIM; i += blockDim.x) sW[i] = W1[i];
    if (t < H_DIM) { sb[t] = b1[t]; s_sum[t] = 0.0f; s_sq[t] = 0.0f; }
    __syncthreads();

    int row = blockIdx.x * blockDim.x + t;
    float f[C_IN];
#pragma unroll
    for (int c = 0; c < C_IN; c++) f[c] = feat[row * C_IN + c];

    int lane = t & 31;
#pragma unroll
    for (int h = 0; h < H_DIM; h++) {
        float a = sb[h];
#pragma unroll
        for (int c = 0; c < C_IN; c++) a = fmaf(f[c], sW[c * H_DIM + h], a);
        g_z1[h * N_PTS + row] = a;
        float v = a, v2 = a * a;
#pragma unroll
        for (int o = 16; o; o >>= 1) {
            v  += __shfl_down_sync(FULLMASK, v,  o);
            v2 += __shfl_down_sync(FULLMASK, v2, o);
        }
        if (lane == 0) { atomicAdd(&s_sum[h], v); atomicAdd(&s_sq[h], v2); }
    }
    __syncthreads();
    if (t < H_DIM) {
        atomicAdd(&g_bn[t], s_sum[t]);
        atomicAdd(&g_bn[H_DIM + t], s_sq[t]);
    }
}

// ---------------- MLP stage 2: 2 threads per row ----------------
#define M2_ROWS 128
__global__ void k_mlp2(const float* __restrict__ W2,
                       const float* __restrict__ b2,
                       const float* __restrict__ g1,
                       const float* __restrict__ be1) {
    __shared__ float sW[H_DIM * H_DIM];
    __shared__ float s_mu[H_DIM], s_rs[H_DIM], s_g[H_DIM], s_be[H_DIM], s_b2[H_DIM];
    __shared__ float s_sum[H_DIM], s_sq[H_DIM];
    int t = threadIdx.x;
    for (int i = t; i < H_DIM * H_DIM; i += blockDim.x) sW[i] = W2[i];
    if (t < H_DIM) {
        float mu  = g_bn[t] * (1.0f / N_PTS);
        float var = g_bn[H_DIM + t] * (1.0f / N_PTS) - mu * mu;
        s_mu[t] = mu;
        s_rs[t] = rsqrtf(var + 1e-5f);
        s_g[t] = g1[t]; s_be[t] = be1[t]; s_b2[t] = b2[t];
        s_sum[t] = 0.0f; s_sq[t] = 0.0f;
    }
    __syncthreads();

    int half = t >> 7;
    int r    = t & (M2_ROWS - 1);
    int row  = blockIdx.x * M2_ROWS + r;

    float h1[H_DIM];
#pragma unroll
    for (int h = 0; h < H_DIM; h++) {
        float x = g_z1[h * N_PTS + row];
        x = s_g[h] * (x - s_mu[h]) * s_rs[h] + s_be[h];
        h1[h] = gelu_exact(x);
    }

    int lane = t & 31;
    int j0 = half * 32;
    for (int jj = 0; jj < 32; jj++) {
        int j = j0 + jj;
        float acc = s_b2[j];
#pragma unroll
        for (int h = 0; h < H_DIM; h++) acc = fmaf(h1[h], sW[h * H_DIM + j], acc);
        g_z2[j * N_PTS + row] = acc;
        float v = acc, v2 = acc * acc;
#pragma unroll
        for (int o = 16; o; o >>= 1) {
            v  += __shfl_down_sync(FULLMASK, v,  o);
            v2 += __shfl_down_sync(FULLMASK, v2, o);
        }
        if (lane == 0) { atomicAdd(&s_sum[j], v); atomicAdd(&s_sq[j], v2); }
    }
    __syncthreads();
    if (t < H_DIM) {
        atomicAdd(&g_bn[2 * H_DIM + t], s_sum[t]);
        atomicAdd(&g_bn[3 * H_DIM + t], s_sq[t]);
    }
}

// ---------------- MLP stage 3 ----------------
__global__ void k_mlp3(const float* __restrict__ W3,
                       const float* __restrict__ b3,
                       const float* __restrict__ g2,
                       const float* __restrict__ be2) {
    __shared__ float s_mu[H_DIM], s_rs[H_DIM], s_g[H_DIM], s_be[H_DIM], s_w3[H_DIM];
    __shared__ float s_b3;
    int t = threadIdx.x;
    if (t < H_DIM) {
        float mu  = g_bn[2 * H_DIM + t] * (1.0f / N_PTS);
        float var = g_bn[3 * H_DIM + t] * (1.0f / N_PTS) - mu * mu;
        s_mu[t] = mu;
        s_rs[t] = rsqrtf(var + 1e-5f);
        s_g[t] = g2[t]; s_be[t] = be2[t]; s_w3[t] = W3[t];
    }
    if (t == 0) s_b3 = b3[0];
    __syncthreads();

    int row = blockIdx.x * blockDim.x + t;
    float acc = s_b3;
#pragma unroll
    for (int h = 0; h < H_DIM; h++) {
        float x = g_z2[h * N_PTS + row];
        x = s_g[h] * (x - s_mu[h]) * s_rs[h] + s_be[h];
        x = gelu_exact(x);
        acc = fmaf(x, s_w3[h], acc);
    }
    g_s[row] = 1.0f / (1.0f + expf(-acc));
}

// ---------------- KNN: warp/query, exact (v,idx) top-32 ----------------------
// Composite lexicographic order (v asc, idx asc) == stable jax top_k order.
// Insert chain has NO memory ops: idx is prefetched with the candidate.
__device__ __forceinline__ void insert_one(
    float cv, int cidx, float& keyv, int& kidx, float& tauv, int lane
) {
    unsigned le = __ballot_sync(FULLMASK,
        (keyv < cv) || (keyv == cv && kidx <= cidx));
    int pos = __popc(le);                 // uniform; pos==32 -> no-op
    float upv = __shfl_up_sync(FULLMASK, keyv, 1);
    int   upi = __shfl_up_sync(FULLMASK, kidx, 1);
    if (lane >= pos) {
        keyv = (lane == pos) ? cv : upv;
        kidx = (lane == pos) ? cidx : upi;
    }
    tauv = __shfl_sync(FULLMASK, keyv, 31);
}

__device__ __forceinline__ void scan_range(
    int st, int en, int lane,
    float ax, float ay, float az,
    float& keyv, int& kidx, float& tauv
) {
    for (int c = st; c < en; c += 32) {
        int i = c + lane;
        float v = FLT_MAX;
        int ci = 0;
        if (i < en) {
            float4 p = g_bpts[i];
            v  = fmaf(ax, p.x, fmaf(ay, p.y, fmaf(az, p.z, p.w)));
            ci = g_bidx[i];               // prefetched: keeps LDG out of chain
        }
        int cnt = min(32, en - c);
        unsigned act = (cnt == 32) ? FULLMASK : ((1u << cnt) - 1u);
        unsigned m = __ballot_sync(FULLMASK, v <= tauv) & act;
        while (m) {                       // warp-uniform; LSB first = idx order
            int src = __ffs(m) - 1;
            m &= m - 1;
            float cv  = __shfl_sync(FULLMASK, v,  src);
            int   cix = __shfl_sync(FULLMASK, ci, src);
            insert_one(cv, cix, keyv, kidx, tauv, lane);
        }
    }
}

__global__ void __launch_bounds__(32 * QPB)
k_knn(const float* __restrict__ coords) {
    __shared__ float s_red[QPB][5];

    int t = threadIdx.x;
    int lane = t & 31, w = t >> 5;
    int qi = blockIdx.x * QPB + w;
    int sbase_bins = (qi >> 13) * NBINS_SCENE;

    float qx = coords[qi * 3 + 0];
    float qy = coords[qi * 3 + 1];
    float qz = coords[qi * 3 + 2];
    float qn = fmaf(qx, qx, fmaf(qy, qy, qz * qz));
    float ax = -2.0f * qx, ay = -2.0f * qy, az = -2.0f * qz;

    int bx = bin_of(qx), by = bin_of(qy), bz = bin_of(qz);
    float lx = qx - (-1.0f + bx * BINW), rx = BINW - lx;
    float ly = qy - (-1.0f + by * BINW), ry = BINW - ly;
    float lz = qz - (-1.0f + bz * BINW), rz = BINW - lz;
    float mar = fmaxf(fminf(fminf(fminf(lx, rx), fminf(ly, ry)), fminf(lz, rz)), 0.0f);

    // ---- boot: home row, first 32 candidates via warp bitonic sort ----
    int hx0 = max(0, bx - 1), hx1 = min(NB - 1, bx + 1);
    int rowb_home = sbase_bins + bz * 64 + by * 8;
    int hst = g_bstart[rowb_home + hx0], hen = g_bend[rowb_home + hx1];

    float keyv; int kidx; float tauv;
    {
        int cnt = min(32, hen - hst);
        int i = hst + lane;
        float v = FLT_MAX;
        int ci = 0x40000000 + lane;       // unique dummies keep order strict
        if (lane < cnt) {
            float4 p = g_bpts[i];
            v  = fmaf(ax, p.x, fmaf(ay, p.y, fmaf(az, p.z, p.w)));
            ci = g_bidx[i];
        }
        // full bitonic sort ascending by (v, idx)
#pragma unroll
        for (int k = 2; k <= 32; k <<= 1) {
#pragma unroll
            for (int j = k >> 1; j > 0; j >>= 1) {
                float ov = __shfl_xor_sync(FULLMASK, v, j);
                int   oi = __shfl_xor_sync(FULLMASK, ci, j);
                bool dirDesc = (lane & k) != 0;
                bool upper   = (lane & j) != 0;
                bool wantMin = (upper == dirDesc);
                bool otherSmaller = (ov < v) || (ov == v && oi < ci);
                bool take = wantMin ? otherSmaller : !otherSmaller;
                if (take) { v = ov; ci = oi; }
            }
        }
        keyv = v; kidx = ci;
        tauv = __shfl_sync(FULLMASK, keyv, 31);
        // rest of home row
        scan_range(hst + 32, hen, lane, ax, ay, az, keyv, kidx, tauv);
    }

    // ---- Phase A: rest of 3x3x3 cube (skip home row) ----
    {
        int z0 = max(0, bz - 1), z1 = min(NB - 1, bz + 1);
        int y0 = max(0, by - 1), y1 = min(NB - 1, by + 1);
        for (int cz = z0; cz <= z1; cz++)
            for (int cy = y0; cy <= y1; cy++) {
                if (cz == bz && cy == by) continue;
                int rowb = sbase_bins + cz * 64 + cy * 8;
                scan_range(g_bstart[rowb + hx0], g_bend[rowb + hx1],
                           lane, ax, ay, az, keyv, kidx, tauv);
            }
    }

    // ---- Phase B: shells sigma >= 2, exact termination ----
    for (int sig = 2; sig < NB; sig++) {
        float dmin = (sig - 1) * BINW + mar;
        float d2tau = tauv + qn + 1e-4f;
        if (dmin * dmin > d2tau) break;
        for (int dz = -sig; dz <= sig; dz++) {
            int cz = bz + dz;
            if (cz < 0 || cz >= NB) continue;
            for (int dy = -sig; dy <= sig; dy++) {
                int cy = by + dy;
                if (cy < 0 || cy >= NB) continue;
                int rowb = sbase_bins + cz * 64 + cy * 8;
                if (abs(dz) == sig || abs(dy) == sig) {
                    int x0 = max(0, bx - sig), x1 = min(NB - 1, bx + sig);
                    scan_range(g_bstart[rowb + x0], g_bend[rowb + x1],
                               lane, ax, ay, az, keyv, kidx, tauv);
                } else {
                    int cxl = bx - sig, cxr = bx + sig;
                    if (cxl >= 0)
                        scan_range(g_bstart[rowb + cxl], g_bend[rowb + cxl],
                                   lane, ax, ay, az, keyv, kidx, tauv);
                    if (cxr < NB)
                        scan_range(g_bstart[rowb + cxr], g_bend[rowb + cxr],
                                   lane, ax, ay, az, keyv, kidx, tauv);
                }
            }
        }
    }

    // ---- fused loss: neighbor k lives in lane k (exact sorted order) ----
    float si = g_s[qi];
    int j = kidx;
    float sj = g_s[j];
    float ad = fabsf(si - sj);
    float num = 0.0f, den = 0.0f, lp = 0.0f, ln_ = 0.0f, nm = 0.0f;

    if (lane < KN) {
        float dx = qx - coords[j * 3 + 0];
        float dy = qy - coords[j * 3 + 1];
        float dz = qz - coords[j * 3 + 2];
        float d2 = fmaf(dz, dz, fmaf(dy, dy, dx * dx));
        float d  = sqrtf(fmaxf(d2, 1e-24f));
        float wq = expf(-d * 10.0f);
        num = wq * ad * ad;
        den = wq;
        float sg = 1.0f / (1.0f + expf(-2.0f * (1.0f - ad)));
        lp = logf(sg + 1e-8f);
        if (lane < KS) nm = sj;
    } else {
        float sg = 1.0f / (1.0f + expf(-2.0f * (1.0f - ad)));
        ln_ = logf(1.0f - sg + 1e-8f);
    }

#pragma unroll
    for (int o = 16; o; o >>= 1) {
        num += __shfl_down_sync(FULLMASK, num, o);
        den += __shfl_down_sync(FULLMASK, den, o);
        lp  += __shfl_down_sync(FULLMASK, lp,  o);
        ln_ += __shfl_down_sync(FULLMASK, ln_, o);
        nm  += __shfl_down_sync(FULLMASK, nm,  o);
    }
    if (lane == 0) {
        nm *= (1.0f / KS);
        float sm = (si - nm) * (si - nm);
        s_red[w][0] = num; s_red[w][1] = den; s_red[w][2] = lp;
        s_red[w][3] = ln_; s_red[w][4] = sm;
    }
    __syncthreads();
    if (t == 0) {
        double a0 = 0, a1 = 0, a2 = 0, a3 = 0, a4 = 0;
#pragma unroll
        for (int v = 0; v < QPB; v++) {
            a0 += (double)s_red[v][0];
            a1 += (double)s_red[v][1];
            a2 += (double)s_red[v][2];
            a3 += (double)s_red[v][3];
            a4 += (double)s_red[v][4];
        }
        atomicAdd(&g_acc[0], a0);
        atomicAdd(&g_acc[1], a1);
        atomicAdd(&g_acc[2], a2);
        atomicAdd(&g_acc[3], a3);
        atomicAdd(&g_acc[4], a4);
    }
}

__global__ void k_fin(float* __restrict__ out) {
    if (threadIdx.x == 0) {
        double loc = g_acc[0] / fmax(g_acc[1], 1e-8);
        double inv = 1.0 / ((double)N_PTS * (double)KN);
        double pos = -g_acc[2] * inv;
        double neg = -g_acc[3] * inv;
        double sm  = g_acc[4] / (double)N_PTS;
        out[0] = (float)(loc + 0.5 * (pos + neg) + 0.2 * sm);
    }
}

// ---------------- launch ----------------
extern "C" void kernel_launch(void* const* d_in, const int* in_sizes, int n_in,
                              void* d_out, int out_size) {
    const float* feat   = (const float*)d_in[0];
    const float* coords = (const float*)d_in[1];
    const float* W1 = (const float*)d_in[2];
    const float* b1 = (const float*)d_in[3];
    const float* g1 = (const float*)d_in[4];
    const float* be1 = (const float*)d_in[5];
    const float* W2 = (const float*)d_in[6];
    const float* b2 = (const float*)d_in[7];
    const float* g2 = (const float*)d_in[8];
    const float* be2 = (const float*)d_in[9];
    const float* W3 = (const float*)d_in[10];
    const float* b3 = (const float*)d_in[11];
    float* out = (float*)d_out;

    k_zero<<<8, 256>>>();
    k_count<<<N_PTS / 256, 256>>>(coords);
    k_scan<<<1, 1024>>>();
    k_scatter<<<N_PTS / 256, 256>>>(coords);
    k_mlp1<<<N_PTS / 256, 256>>>(feat, W1, b1);
    k_mlp2<<<N_PTS / M2_ROWS, 256>>>(W2, b2, g1, be1);
    k_mlp3<<<N_PTS / 256, 256>>>(W3, b3, g2, be2);
    k_knn<<<N_PTS / QPB, 32 * QPB>>>(coords);
    k_fin<<<1, 1>>>(out);
}